// round 8
// baseline (speedup 1.0000x reference)
#include <cuda_runtime.h>
#include <cuda_bf16.h>
#include <mma.h>
#include <cstdint>

using namespace nvcuda;

#define N_NODES 50000
#define N_PAD   50048
#define N_EDGES 800000
#define D_IN    256
#define D_HID2  256
#define D_HID   128
#define D_MLP   64
#define D_OUT   64

// ---------------- scratch ----------------
__device__ float g_hpre[(size_t)N_PAD * D_HID2];
__device__ float g_hcur[(size_t)N_PAD * D_HID2];
__device__ float g_hidden[(size_t)N_PAD * D_MLP];
__device__ float g_deg_out_inv[N_NODES];
__device__ float g_deg_in_inv[N_NODES];
__device__ int   g_deg_out_cnt[N_NODES];
__device__ int   g_deg_in_cnt[N_NODES];
__device__ int   g_row_ptr[N_NODES + 1];
__device__ int   g_fill_ptr[N_NODES];
__device__ int   g_blk[64];
__device__ int   g_csr_src[N_EDGES];

template<int SEL>
__device__ __forceinline__ const float* select_in(const float* ext) {
    if constexpr (SEL == 1) return g_hcur;
    else if constexpr (SEL == 2) return g_hidden;
    else return ext;
}
template<int SEL>
__device__ __forceinline__ float* select_out(float* ext) {
    if constexpr (SEL == 1) return g_hpre;
    else if constexpr (SEL == 2) return g_hidden;
    else return ext;
}

// ---------------- degree / CSR ----------------

__global__ void zero_counts_kernel(int n) {
    int i = blockIdx.x * blockDim.x + threadIdx.x;
    if (i < n) { g_deg_out_cnt[i] = 0; g_deg_in_cnt[i] = 0; }
}

__global__ void degree_kernel(const int* __restrict__ ei, int E) {
    int e = blockIdx.x * blockDim.x + threadIdx.x;
    if (e < E) {
        atomicAdd(&g_deg_out_cnt[ei[e]], 1);
        atomicAdd(&g_deg_in_cnt[ei[E + e]], 1);
    }
}

__global__ void inv_kernel(int n) {
    int i = blockIdx.x * blockDim.x + threadIdx.x;
    if (i < n) {
        g_deg_out_inv[i] = rsqrtf(fmaxf((float)g_deg_out_cnt[i], 1.0f));
        g_deg_in_inv[i]  = rsqrtf(fmaxf((float)g_deg_in_cnt[i], 1.0f));
    }
}

// layer-1 input prescale: g_hcur = x * deg_out_inv (row-wise)
__global__ void scale_x_kernel(const float* __restrict__ x) {
    int idx = blockIdx.x * blockDim.x + threadIdx.x;
    if (idx >= N_NODES * (D_IN / 4)) return;
    int row = idx / (D_IN / 4);
    float sc = g_deg_out_inv[row];
    float4 v = ((const float4*)x)[idx];
    v.x *= sc; v.y *= sc; v.z *= sc; v.w *= sc;
    ((float4*)g_hcur)[idx] = v;
}

__global__ void scan1_kernel(int n) {
    __shared__ int s[1024];
    int tid = threadIdx.x;
    int i = blockIdx.x * 1024 + tid;
    int v = (i < n) ? g_deg_in_cnt[i] : 0;
    s[tid] = v;
    __syncthreads();
    #pragma unroll
    for (int off = 1; off < 1024; off <<= 1) {
        int t = 0;
        if (tid >= off) t = s[tid - off];
        __syncthreads();
        s[tid] += t;
        __syncthreads();
    }
    if (i < n) g_row_ptr[i + 1] = s[tid];
    if (tid == 1023) g_blk[blockIdx.x] = s[1023];
}

__global__ void scan2_kernel(int nb) {
    if (threadIdx.x == 0 && blockIdx.x == 0) {
        int acc = 0;
        for (int i = 0; i < nb; i++) { int t = g_blk[i]; g_blk[i] = acc; acc += t; }
    }
}

__global__ void scan3_kernel(int n) {
    int i = blockIdx.x * 1024 + threadIdx.x;
    if (i < n) g_row_ptr[i + 1] += g_blk[blockIdx.x];
    if (i == 0) g_row_ptr[0] = 0;
}

__global__ void copy_fill_kernel(int n) {
    int i = blockIdx.x * blockDim.x + threadIdx.x;
    if (i < n) g_fill_ptr[i] = g_row_ptr[i];
}

__global__ void fill_csr_kernel(const int* __restrict__ ei, int E) {
    int e = blockIdx.x * blockDim.x + threadIdx.x;
    if (e < E) {
        int d = ei[E + e];
        int pos = atomicAdd(&g_fill_ptr[d], 1);
        g_csr_src[pos] = ei[e];
    }
}

// ---------------- tf32 WMMA GEMM: C = A @ B (pure) ----------------
// BM=128, BK=16, 256 threads, 8 warps (4x2). Warp tile 32 x (BN/2).
// Double-buffered smem (one __syncthreads per stage) + register prefetch.
// RN tf32 rounding applied at smem store.
template<int BN, int ASEL, int CSEL>
__global__ __launch_bounds__(256)
void gemm_tf32_kernel(const float* __restrict__ Aext, const float* __restrict__ B,
                      int M, int N, int K)
{
    constexpr int BM = 128, BK = 16;
    constexpr int LDA = BK + 4;      // 20
    constexpr int LDB = BN + 8;      // 136 / 72
    constexpr int WN  = BN / 2;
    constexpr int NF  = WN / 16;     // 4 / 2
    constexpr int BL  = BN / 64;     // B float4 loads per thread (2 / 1)
    constexpr int BC4 = BN / 4;      // float4s per B row

    const float* A = select_in<ASEL>(Aext);
    float* C = select_out<CSEL>(nullptr);

    __shared__ float As[2][BM][LDA];
    __shared__ float Bs[2][BK][LDB];

    const int tid  = threadIdx.x;
    const int warp = tid >> 5;
    const int wr   = warp >> 1;
    const int wc   = warp & 1;
    const int row0 = blockIdx.y * BM;
    const int col0 = blockIdx.x * BN;

    // A-load mapping: 512 float4 per stage -> 2 per thread
    const int ar0 = tid >> 2;                 // lin = tid:       row 0..63
    const int ac0 = (tid & 3) << 2;
    const int ar1 = (tid + 256) >> 2;         // lin = tid+256:   row 64..127
    const int ac1 = ac0;

    wmma::fragment<wmma::accumulator, 16, 16, 8, float> acc[2][NF];
    #pragma unroll
    for (int i = 0; i < 2; i++)
        #pragma unroll
        for (int j = 0; j < NF; j++) wmma::fill_fragment(acc[i][j], 0.0f);

    float4 aP[2], bP[BL];

    auto loadA = [&](int k0) {
        int g0 = row0 + ar0, g1 = row0 + ar1;
        aP[0] = make_float4(0.f, 0.f, 0.f, 0.f);
        aP[1] = make_float4(0.f, 0.f, 0.f, 0.f);
        if (g0 < M) aP[0] = *(const float4*)&A[(size_t)g0 * K + k0 + ac0];
        if (g1 < M) aP[1] = *(const float4*)&A[(size_t)g1 * K + k0 + ac1];
    };
    auto loadB = [&](int k0) {
        #pragma unroll
        for (int l = 0; l < BL; l++) {
            int lin = tid + l * 256;
            int r = lin / BC4, c4 = (lin % BC4) * 4;
            bP[l] = *(const float4*)&B[(size_t)(k0 + r) * N + col0 + c4];
        }
    };
    auto storeTiles = [&](int buf) {
        As[buf][ar0][ac0 + 0] = wmma::__float_to_tf32(aP[0].x);
        As[buf][ar0][ac0 + 1] = wmma::__float_to_tf32(aP[0].y);
        As[buf][ar0][ac0 + 2] = wmma::__float_to_tf32(aP[0].z);
        As[buf][ar0][ac0 + 3] = wmma::__float_to_tf32(aP[0].w);
        As[buf][ar1][ac1 + 0] = wmma::__float_to_tf32(aP[1].x);
        As[buf][ar1][ac1 + 1] = wmma::__float_to_tf32(aP[1].y);
        As[buf][ar1][ac1 + 2] = wmma::__float_to_tf32(aP[1].z);
        As[buf][ar1][ac1 + 3] = wmma::__float_to_tf32(aP[1].w);
        #pragma unroll
        for (int l = 0; l < BL; l++) {
            int lin = tid + l * 256;
            int r = lin / BC4, c4 = (lin % BC4) * 4;
            Bs[buf][r][c4 + 0] = wmma::__float_to_tf32(bP[l].x);
            Bs[buf][r][c4 + 1] = wmma::__float_to_tf32(bP[l].y);
            Bs[buf][r][c4 + 2] = wmma::__float_to_tf32(bP[l].z);
            Bs[buf][r][c4 + 3] = wmma::__float_to_tf32(bP[l].w);
        }
    };

    const int S = K / BK;
    loadA(0); loadB(0);
    storeTiles(0);
    __syncthreads();

    for (int s = 0; s < S; s++) {
        int cur = s & 1;
        if (s + 1 < S) { loadA((s + 1) * BK); loadB((s + 1) * BK); }

        #pragma unroll
        for (int kk = 0; kk < BK; kk += 8) {
            wmma::fragment<wmma::matrix_a, 16, 16, 8, wmma::precision::tf32, wmma::row_major> af[2];
            #pragma unroll
            for (int i = 0; i < 2; i++)
                wmma::load_matrix_sync(af[i], &As[cur][wr * 32 + i * 16][kk], LDA);
            wmma::fragment<wmma::matrix_b, 16, 16, 8, wmma::precision::tf32, wmma::row_major> bf[NF];
            #pragma unroll
            for (int j = 0; j < NF; j++)
                wmma::load_matrix_sync(bf[j], &Bs[cur][kk][wc * WN + j * 16], LDB);
            #pragma unroll
            for (int i = 0; i < 2; i++)
                #pragma unroll
                for (int j = 0; j < NF; j++)
                    wmma::mma_sync(acc[i][j], af[i], bf[j], acc[i][j]);
        }

        if (s + 1 < S) storeTiles(1 - cur);
        __syncthreads();
    }

    #pragma unroll
    for (int i = 0; i < 2; i++)
        #pragma unroll
        for (int j = 0; j < NF; j++) {
            int r = row0 + wr * 32 + i * 16;
            int c = col0 + wc * WN + j * 16;
            wmma::store_matrix_sync(&C[(size_t)r * N + c], acc[i][j], N, wmma::mem_row_major);
        }
}

// ---------------- SIMT GEMM (final MLP layer; guarded d_out store) ----------------
#define GTHREADS 256
template<int BN, int ASEL, int CSEL, int USE_BIAS, int DO_RELU, int ABR>
__global__ __launch_bounds__(GTHREADS)
void gemm128_kernel(const float* __restrict__ Aext, const float* __restrict__ B,
                    float* __restrict__ Cext, int M, int N, int K,
                    const float* __restrict__ bias, const float* __restrict__ abias)
{
    constexpr int BM = 128;
    constexpr int BK = 8;
    constexpr int TM = 8;
    constexpr int TN = BN / 16;

    const float* A = select_in<ASEL>(Aext);
    float* C = select_out<CSEL>(Cext);

    __shared__ float As[BK][BM + 4];
    __shared__ float Bs[BK][BN];

    const int tid = threadIdx.x;
    const int tx = tid % 16;
    const int ty = tid / 16;
    const int row0 = blockIdx.y * BM;
    const int col0 = blockIdx.x * BN;

    const int arow = tid / 2;
    const int ac4  = (tid % 2) * 4;
    const int gA   = row0 + arow;

    const int brow = (BN == 128) ? (tid / 32) : (tid / 16);
    const int bc4  = (BN == 128) ? ((tid % 32) * 4) : ((tid % 16) * 4);
    const bool bactive = (BN == 128) ? true : (tid < 128);

    float acc[TM][TN];
    #pragma unroll
    for (int i = 0; i < TM; i++)
        #pragma unroll
        for (int j = 0; j < TN; j++) acc[i][j] = 0.0f;

    float4 av = make_float4(0.f, 0.f, 0.f, 0.f);
    if (gA < M) {
        av = *(const float4*)&A[(size_t)gA * K + ac4];
        if constexpr (ABR) {
            av.x = fmaxf(av.x + abias[ac4 + 0], 0.f);
            av.y = fmaxf(av.y + abias[ac4 + 1], 0.f);
            av.z = fmaxf(av.z + abias[ac4 + 2], 0.f);
            av.w = fmaxf(av.w + abias[ac4 + 3], 0.f);
        }
    }
    float4 bv = make_float4(0.f, 0.f, 0.f, 0.f);
    if (bactive) bv = *(const float4*)&B[(size_t)brow * N + col0 + bc4];

    for (int k0 = 0; k0 < K; k0 += BK) {
        As[ac4 + 0][arow] = av.x;
        As[ac4 + 1][arow] = av.y;
        As[ac4 + 2][arow] = av.z;
        As[ac4 + 3][arow] = av.w;
        if (bactive) *(float4*)&Bs[brow][bc4] = bv;
        __syncthreads();

        if (k0 + BK < K) {
            av = make_float4(0.f, 0.f, 0.f, 0.f);
            if (gA < M) {
                av = *(const float4*)&A[(size_t)gA * K + (k0 + BK) + ac4];
                if constexpr (ABR) {
                    av.x = fmaxf(av.x + abias[k0 + BK + ac4 + 0], 0.f);
                    av.y = fmaxf(av.y + abias[k0 + BK + ac4 + 1], 0.f);
                    av.z = fmaxf(av.z + abias[k0 + BK + ac4 + 2], 0.f);
                    av.w = fmaxf(av.w + abias[k0 + BK + ac4 + 3], 0.f);
                }
            }
            if (bactive) bv = *(const float4*)&B[(size_t)(k0 + BK + brow) * N + col0 + bc4];
        }

        #pragma unroll
        for (int k = 0; k < BK; k++) {
            float a[TM], b[TN];
            #pragma unroll
            for (int q = 0; q < TM / 4; q++)
                *(float4*)&a[q * 4] = *(const float4*)&As[k][ty * TM + q * 4];
            #pragma unroll
            for (int q = 0; q < TN / 4; q++)
                *(float4*)&b[q * 4] = *(const float4*)&Bs[k][tx * TN + q * 4];
            #pragma unroll
            for (int i = 0; i < TM; i++)
                #pragma unroll
                for (int j = 0; j < TN; j++)
                    acc[i][j] += a[i] * b[j];
        }
        __syncthreads();
    }

    #pragma unroll
    for (int i = 0; i < TM; i++) {
        int r = row0 + ty * TM + i;
        if (r >= M) continue;
        #pragma unroll
        for (int j = 0; j < TN; j += 4) {
            int c = col0 + tx * TN + j;
            float4 v = *(float4*)&acc[i][j];
            if constexpr (USE_BIAS) {
                v.x += bias[c + 0]; v.y += bias[c + 1];
                v.z += bias[c + 2]; v.w += bias[c + 3];
            }
            if constexpr (DO_RELU) {
                v.x = fmaxf(v.x, 0.f); v.y = fmaxf(v.y, 0.f);
                v.z = fmaxf(v.z, 0.f); v.w = fmaxf(v.w, 0.f);
            }
            *(float4*)&C[(size_t)r * N + c] = v;
        }
    }
}

// ---------------- aggregation (float4; 256 threads; 4-edge unroll) ----------------
template<int D, int OSEL, int PRESCALE>
__global__ __launch_bounds__(256)
void agg4_kernel(float* __restrict__ outExt, const float* __restrict__ bias)
{
    constexpr int TPN = D / 4;                 // 64 (D=256) / 32 (D=128)
    constexpr int NPB = 256 / TPN;             // 4 / 8
    float* out;
    if constexpr (OSEL == 1) out = g_hcur;
    else out = outExt;

    const int lane = threadIdx.x % TPN;
    const int node = blockIdx.x * NPB + threadIdx.x / TPN;
    if (node >= N_NODES) return;

    const int s = g_row_ptr[node];
    const int e = g_row_ptr[node + 1];
    const float4* __restrict__ hp = (const float4*)g_hpre;
    const int* __restrict__ csr = g_csr_src;

    float4 acc0 = make_float4(0.f, 0.f, 0.f, 0.f);
    float4 acc1 = make_float4(0.f, 0.f, 0.f, 0.f);
    int i = s;
    for (; i + 3 < e; i += 4) {
        int s0 = csr[i];
        int s1 = csr[i + 1];
        int s2 = csr[i + 2];
        int s3 = csr[i + 3];
        float4 v0 = hp[(size_t)s0 * TPN + lane];
        float4 v1 = hp[(size_t)s1 * TPN + lane];
        float4 v2 = hp[(size_t)s2 * TPN + lane];
        float4 v3 = hp[(size_t)s3 * TPN + lane];
        acc0.x += v0.x; acc0.y += v0.y; acc0.z += v0.z; acc0.w += v0.w;
        acc1.x += v1.x; acc1.y += v1.y; acc1.z += v1.z; acc1.w += v1.w;
        acc0.x += v2.x; acc0.y += v2.y; acc0.z += v2.z; acc0.w += v2.w;
        acc1.x += v3.x; acc1.y += v3.y; acc1.z += v3.z; acc1.w += v3.w;
    }
    for (; i < e; i++) {
        int s0 = csr[i];
        float4 v0 = hp[(size_t)s0 * TPN + lane];
        acc0.x += v0.x; acc0.y += v0.y; acc0.z += v0.z; acc0.w += v0.w;
    }
    acc0.x += acc1.x; acc0.y += acc1.y; acc0.z += acc1.z; acc0.w += acc1.w;

    const float sc = g_deg_in_inv[node];
    float osc = 1.0f;
    if constexpr (PRESCALE) osc = g_deg_out_inv[node];
    float4 bb = *(const float4*)&bias[lane * 4];
    float4 r;
    r.x = fmaxf(acc0.x * sc + bb.x, 0.f) * osc;
    r.y = fmaxf(acc0.y * sc + bb.y, 0.f) * osc;
    r.z = fmaxf(acc0.z * sc + bb.z, 0.f) * osc;
    r.w = fmaxf(acc0.w * sc + bb.w, 0.f) * osc;
    *(float4*)&out[(size_t)node * D + lane * 4] = r;
}

// ---------------- launch ----------------
extern "C" void kernel_launch(void* const* d_in, const int* in_sizes, int n_in,
                              void* d_out, int out_size)
{
    const float* x   = (const float*)d_in[0];
    const int*   ei  = (const int*)d_in[1];
    const float* W1  = (const float*)d_in[2];
    const float* b1  = (const float*)d_in[3];
    const float* W2  = (const float*)d_in[4];
    const float* b2  = (const float*)d_in[5];
    const float* W3  = (const float*)d_in[6];
    const float* b3  = (const float*)d_in[7];
    const float* mW1 = (const float*)d_in[8];
    const float* mb1 = (const float*)d_in[9];
    const float* mW2 = (const float*)d_in[10];
    const float* mb2 = (const float*)d_in[11];

    const int N = in_sizes[0] / D_IN;       // 50000
    const int E = in_sizes[1] / 2;          // 800000

    float* out      = (float*)d_out;
    float* h_last   = (float*)d_out + (size_t)N * D_OUT;

    const int T = 256;
    const int nbN = (N + T - 1) / T;
    const int nbE = (E + T - 1) / T;
    const int nbScan = (N + 1023) / 1024;
    const int tfRows = (N + 127) / 128;     // 391

    // ---- degrees + CSR build + input prescale ----
    zero_counts_kernel<<<nbN, T>>>(N);
    degree_kernel<<<nbE, T>>>(ei, E);
    inv_kernel<<<nbN, T>>>(N);
    scale_x_kernel<<<(N * (D_IN / 4) + T - 1) / T, T>>>(x);
    scan1_kernel<<<nbScan, 1024>>>(N);
    scan2_kernel<<<1, 32>>>(nbScan);
    scan3_kernel<<<nbScan, 1024>>>(N);
    copy_fill_kernel<<<nbN, T>>>(N);
    fill_csr_kernel<<<nbE, T>>>(ei, E);

    // ---- layer 1 ----
    {
        dim3 grid(D_HID2 / 128, tfRows);
        gemm_tf32_kernel<128, 1, 1><<<grid, 256>>>(nullptr, W1, N, D_HID2, D_IN);
        agg4_kernel<D_HID2, 1, 1><<<(N + 3) / 4, 256>>>(nullptr, b1);
    }
    // ---- layer 2 ----
    {
        dim3 grid(D_HID2 / 128, tfRows);
        gemm_tf32_kernel<128, 1, 1><<<grid, 256>>>(nullptr, W2, N, D_HID2, D_HID2);
        agg4_kernel<D_HID2, 1, 1><<<(N + 3) / 4, 256>>>(nullptr, b2);
    }
    // ---- layer 3: h_last (unscaled) directly into d_out ----
    {
        dim3 grid(D_HID / 128, tfRows);
        gemm_tf32_kernel<128, 1, 1><<<grid, 256>>>(nullptr, W3, N, D_HID, D_HID2);
        agg4_kernel<D_HID, 0, 0><<<(N + 7) / 8, 256>>>(h_last, b3);
    }
    // ---- MLP layer 1 (tf32, raw GEMM into scratch) ----
    {
        dim3 grid(1, tfRows);
        gemm_tf32_kernel<64, 0, 2><<<grid, 256>>>(h_last, mW1, N, D_MLP, D_HID);
    }
    // ---- MLP layer 2 (SIMT, A-side relu(a+mb1), guarded d_out store) ----
    {
        dim3 grid(D_OUT / 64, tfRows);
        gemm128_kernel<64, 2, 0, 1, 0, 1><<<grid, GTHREADS>>>(nullptr, mW2, out,
                                                              N, D_OUT, D_MLP, mb2, mb1);
    }
}

// round 9
// speedup vs baseline: 1.3537x; 1.3537x over previous
#include <cuda_runtime.h>
#include <cuda_bf16.h>
#include <mma.h>
#include <cstdint>

using namespace nvcuda;

#define N_NODES 50000
#define N_PAD   50048
#define N_EDGES 800000
#define D_IN    256
#define D_HID2  256
#define D_HID   128
#define D_MLP   64
#define D_OUT   64

// ---------------- scratch ----------------
__device__ float g_hpre[(size_t)N_PAD * D_HID2];
__device__ float g_hcur[(size_t)N_PAD * D_HID2];
__device__ float g_hidden[(size_t)N_PAD * D_MLP];
__device__ float g_deg_out_inv[N_NODES];
__device__ float g_deg_in_inv[N_NODES];
__device__ int   g_deg_out_cnt[N_NODES];
__device__ int   g_deg_in_cnt[N_NODES];
__device__ int   g_row_ptr[N_NODES + 1];
__device__ int   g_fill_ptr[N_NODES];
__device__ int   g_blk[64];
__device__ int   g_csr_src[N_EDGES];

template<int SEL>
__device__ __forceinline__ const float* select_in(const float* ext) {
    if constexpr (SEL == 1) return g_hcur;
    else if constexpr (SEL == 2) return g_hidden;
    else return ext;
}
template<int SEL>
__device__ __forceinline__ float* select_out(float* ext) {
    if constexpr (SEL == 1) return g_hpre;
    else if constexpr (SEL == 2) return g_hidden;
    else return ext;
}

// ---------------- degree / CSR ----------------

__global__ void zero_counts_kernel(int n) {
    int i = blockIdx.x * blockDim.x + threadIdx.x;
    if (i < n) { g_deg_out_cnt[i] = 0; g_deg_in_cnt[i] = 0; }
}

__global__ void degree_kernel(const int* __restrict__ ei, int E) {
    int e = blockIdx.x * blockDim.x + threadIdx.x;
    if (e < E) {
        atomicAdd(&g_deg_out_cnt[ei[e]], 1);
        atomicAdd(&g_deg_in_cnt[ei[E + e]], 1);
    }
}

__global__ void inv_kernel(int n) {
    int i = blockIdx.x * blockDim.x + threadIdx.x;
    if (i < n) {
        g_deg_out_inv[i] = rsqrtf(fmaxf((float)g_deg_out_cnt[i], 1.0f));
        g_deg_in_inv[i]  = rsqrtf(fmaxf((float)g_deg_in_cnt[i], 1.0f));
    }
}

__global__ void scan1_kernel(int n) {
    __shared__ int s[1024];
    int tid = threadIdx.x;
    int i = blockIdx.x * 1024 + tid;
    int v = (i < n) ? g_deg_in_cnt[i] : 0;
    s[tid] = v;
    __syncthreads();
    #pragma unroll
    for (int off = 1; off < 1024; off <<= 1) {
        int t = 0;
        if (tid >= off) t = s[tid - off];
        __syncthreads();
        s[tid] += t;
        __syncthreads();
    }
    if (i < n) g_row_ptr[i + 1] = s[tid];
    if (tid == 1023) g_blk[blockIdx.x] = s[1023];
}

__global__ void scan2_kernel(int nb) {
    if (threadIdx.x == 0 && blockIdx.x == 0) {
        int acc = 0;
        for (int i = 0; i < nb; i++) { int t = g_blk[i]; g_blk[i] = acc; acc += t; }
    }
}

__global__ void scan3_kernel(int n) {
    int i = blockIdx.x * 1024 + threadIdx.x;
    if (i < n) g_row_ptr[i + 1] += g_blk[blockIdx.x];
    if (i == 0) g_row_ptr[0] = 0;
}

__global__ void copy_fill_kernel(int n) {
    int i = blockIdx.x * blockDim.x + threadIdx.x;
    if (i < n) g_fill_ptr[i] = g_row_ptr[i];
}

__global__ void fill_csr_kernel(const int* __restrict__ ei, int E) {
    int e = blockIdx.x * blockDim.x + threadIdx.x;
    if (e < E) {
        int d = ei[E + e];
        int pos = atomicAdd(&g_fill_ptr[d], 1);
        g_csr_src[pos] = ei[e];
    }
}

// ---------------- tf32 WMMA GEMM: C = (A * rowscale?) @ B ----------------
// BM=128, BK=32, 256 threads, 8 warps (4x2). Warp tile 32 x (BN/2).
// tf32 RN rounding at smem store; register double-buffered (R7 structure).
// RS: multiply A rows by g_deg_out_inv at load (fused layer-1 prescale).
template<int BN, int ASEL, int CSEL, int RS>
__global__ __launch_bounds__(256)
void gemm_tf32_kernel(const float* __restrict__ Aext, const float* __restrict__ B,
                      int M, int N, int K)
{
    constexpr int BM = 128, BK = 32;
    constexpr int LDA = BK + 8;      // 40
    constexpr int LDB = BN + 8;      // 136 / 72
    constexpr int WN  = BN / 2;      // warp tile N
    constexpr int NF  = WN / 16;     // B frags per warp (4 / 2)
    constexpr int BL  = BN / 32;     // B float4 loads per thread (4 / 2)
    constexpr int BC4 = BN / 4;      // float4s per B row

    const float* A = select_in<ASEL>(Aext);
    float* C = select_out<CSEL>(nullptr);

    __shared__ float As[BM][LDA];
    __shared__ float Bs[BK][LDB];

    const int tid  = threadIdx.x;
    const int warp = tid >> 5;
    const int wr   = warp >> 1;
    const int wc   = warp & 1;
    const int row0 = blockIdx.y * BM;
    const int col0 = blockIdx.x * BN;

    wmma::fragment<wmma::accumulator, 16, 16, 8, float> acc[2][NF];
    #pragma unroll
    for (int i = 0; i < 2; i++)
        #pragma unroll
        for (int j = 0; j < NF; j++) wmma::fill_fragment(acc[i][j], 0.0f);

    float4 aP[4], bP[BL];
    // initial prefetch (k0 = 0)
    #pragma unroll
    for (int l = 0; l < 4; l++) {
        int lin = tid + l * 256;
        int r = lin >> 3, c4 = (lin & 7) << 2;
        int gr = row0 + r;
        float4 v = make_float4(0.f, 0.f, 0.f, 0.f);
        if (gr < M) {
            v = *(const float4*)&A[(size_t)gr * K + c4];
            if constexpr (RS) {
                float sc = g_deg_out_inv[gr];
                v.x *= sc; v.y *= sc; v.z *= sc; v.w *= sc;
            }
        }
        aP[l] = v;
    }
    #pragma unroll
    for (int l = 0; l < BL; l++) {
        int lin = tid + l * 256;
        int r = lin / BC4, c4 = (lin % BC4) * 4;
        bP[l] = *(const float4*)&B[(size_t)r * N + col0 + c4];
    }

    for (int k0 = 0; k0 < K; k0 += BK) {
        // commit prefetched tiles with tf32 RN rounding
        #pragma unroll
        for (int l = 0; l < 4; l++) {
            int lin = tid + l * 256;
            int r = lin >> 3, c4 = (lin & 7) << 2;
            As[r][c4 + 0] = wmma::__float_to_tf32(aP[l].x);
            As[r][c4 + 1] = wmma::__float_to_tf32(aP[l].y);
            As[r][c4 + 2] = wmma::__float_to_tf32(aP[l].z);
            As[r][c4 + 3] = wmma::__float_to_tf32(aP[l].w);
        }
        #pragma unroll
        for (int l = 0; l < BL; l++) {
            int lin = tid + l * 256;
            int r = lin / BC4, c4 = (lin % BC4) * 4;
            Bs[r][c4 + 0] = wmma::__float_to_tf32(bP[l].x);
            Bs[r][c4 + 1] = wmma::__float_to_tf32(bP[l].y);
            Bs[r][c4 + 2] = wmma::__float_to_tf32(bP[l].z);
            Bs[r][c4 + 3] = wmma::__float_to_tf32(bP[l].w);
        }
        __syncthreads();

        // prefetch next tile during compute
        if (k0 + BK < K) {
            #pragma unroll
            for (int l = 0; l < 4; l++) {
                int lin = tid + l * 256;
                int r = lin >> 3, c4 = (lin & 7) << 2;
                int gr = row0 + r;
                float4 v = make_float4(0.f, 0.f, 0.f, 0.f);
                if (gr < M) {
                    v = *(const float4*)&A[(size_t)gr * K + (k0 + BK) + c4];
                    if constexpr (RS) {
                        float sc = g_deg_out_inv[gr];
                        v.x *= sc; v.y *= sc; v.z *= sc; v.w *= sc;
                    }
                }
                aP[l] = v;
            }
            #pragma unroll
            for (int l = 0; l < BL; l++) {
                int lin = tid + l * 256;
                int r = lin / BC4, c4 = (lin % BC4) * 4;
                bP[l] = *(const float4*)&B[(size_t)(k0 + BK + r) * N + col0 + c4];
            }
        }

        #pragma unroll
        for (int kk = 0; kk < BK; kk += 8) {
            wmma::fragment<wmma::matrix_a, 16, 16, 8, wmma::precision::tf32, wmma::row_major> af[2];
            #pragma unroll
            for (int i = 0; i < 2; i++)
                wmma::load_matrix_sync(af[i], &As[wr * 32 + i * 16][kk], LDA);
            wmma::fragment<wmma::matrix_b, 16, 16, 8, wmma::precision::tf32, wmma::row_major> bf[NF];
            #pragma unroll
            for (int j = 0; j < NF; j++)
                wmma::load_matrix_sync(bf[j], &Bs[kk][wc * WN + j * 16], LDB);
            #pragma unroll
            for (int i = 0; i < 2; i++)
                #pragma unroll
                for (int j = 0; j < NF; j++)
                    wmma::mma_sync(acc[i][j], af[i], bf[j], acc[i][j]);
        }
        __syncthreads();
    }

    // full-tile store into padded scratch
    #pragma unroll
    for (int i = 0; i < 2; i++)
        #pragma unroll
        for (int j = 0; j < NF; j++) {
            int r = row0 + wr * 32 + i * 16;
            int c = col0 + wc * WN + j * 16;
            wmma::store_matrix_sync(&C[(size_t)r * N + c], acc[i][j], N, wmma::mem_row_major);
        }
}

// ---------------- SIMT GEMM (final MLP layer; guarded d_out store) ----------------
#define GTHREADS 256
template<int BN, int ASEL, int CSEL, int USE_BIAS, int DO_RELU, int ABR>
__global__ __launch_bounds__(GTHREADS)
void gemm128_kernel(const float* __restrict__ Aext, const float* __restrict__ B,
                    float* __restrict__ Cext, int M, int N, int K,
                    const float* __restrict__ bias, const float* __restrict__ abias)
{
    constexpr int BM = 128;
    constexpr int BK = 8;
    constexpr int TM = 8;
    constexpr int TN = BN / 16;

    const float* A = select_in<ASEL>(Aext);
    float* C = select_out<CSEL>(Cext);

    __shared__ float As[BK][BM + 4];
    __shared__ float Bs[BK][BN];

    const int tid = threadIdx.x;
    const int tx = tid % 16;
    const int ty = tid / 16;
    const int row0 = blockIdx.y * BM;
    const int col0 = blockIdx.x * BN;

    const int arow = tid / 2;
    const int ac4  = (tid % 2) * 4;
    const int gA   = row0 + arow;

    const int brow = (BN == 128) ? (tid / 32) : (tid / 16);
    const int bc4  = (BN == 128) ? ((tid % 32) * 4) : ((tid % 16) * 4);
    const bool bactive = (BN == 128) ? true : (tid < 128);

    float acc[TM][TN];
    #pragma unroll
    for (int i = 0; i < TM; i++)
        #pragma unroll
        for (int j = 0; j < TN; j++) acc[i][j] = 0.0f;

    float4 av = make_float4(0.f, 0.f, 0.f, 0.f);
    if (gA < M) {
        av = *(const float4*)&A[(size_t)gA * K + ac4];
        if constexpr (ABR) {
            av.x = fmaxf(av.x + abias[ac4 + 0], 0.f);
            av.y = fmaxf(av.y + abias[ac4 + 1], 0.f);
            av.z = fmaxf(av.z + abias[ac4 + 2], 0.f);
            av.w = fmaxf(av.w + abias[ac4 + 3], 0.f);
        }
    }
    float4 bv = make_float4(0.f, 0.f, 0.f, 0.f);
    if (bactive) bv = *(const float4*)&B[(size_t)brow * N + col0 + bc4];

    for (int k0 = 0; k0 < K; k0 += BK) {
        As[ac4 + 0][arow] = av.x;
        As[ac4 + 1][arow] = av.y;
        As[ac4 + 2][arow] = av.z;
        As[ac4 + 3][arow] = av.w;
        if (bactive) *(float4*)&Bs[brow][bc4] = bv;
        __syncthreads();

        if (k0 + BK < K) {
            av = make_float4(0.f, 0.f, 0.f, 0.f);
            if (gA < M) {
                av = *(const float4*)&A[(size_t)gA * K + (k0 + BK) + ac4];
                if constexpr (ABR) {
                    av.x = fmaxf(av.x + abias[k0 + BK + ac4 + 0], 0.f);
                    av.y = fmaxf(av.y + abias[k0 + BK + ac4 + 1], 0.f);
                    av.z = fmaxf(av.z + abias[k0 + BK + ac4 + 2], 0.f);
                    av.w = fmaxf(av.w + abias[k0 + BK + ac4 + 3], 0.f);
                }
            }
            if (bactive) bv = *(const float4*)&B[(size_t)(k0 + BK + brow) * N + col0 + bc4];
        }

        #pragma unroll
        for (int k = 0; k < BK; k++) {
            float a[TM], b[TN];
            #pragma unroll
            for (int q = 0; q < TM / 4; q++)
                *(float4*)&a[q * 4] = *(const float4*)&As[k][ty * TM + q * 4];
            #pragma unroll
            for (int q = 0; q < TN / 4; q++)
                *(float4*)&b[q * 4] = *(const float4*)&Bs[k][tx * TN + q * 4];
            #pragma unroll
            for (int i = 0; i < TM; i++)
                #pragma unroll
                for (int j = 0; j < TN; j++)
                    acc[i][j] += a[i] * b[j];
        }
        __syncthreads();
    }

    #pragma unroll
    for (int i = 0; i < TM; i++) {
        int r = row0 + ty * TM + i;
        if (r >= M) continue;
        #pragma unroll
        for (int j = 0; j < TN; j += 4) {
            int c = col0 + tx * TN + j;
            float4 v = *(float4*)&acc[i][j];
            if constexpr (USE_BIAS) {
                v.x += bias[c + 0]; v.y += bias[c + 1];
                v.z += bias[c + 2]; v.w += bias[c + 3];
            }
            if constexpr (DO_RELU) {
                v.x = fmaxf(v.x, 0.f); v.y = fmaxf(v.y, 0.f);
                v.z = fmaxf(v.z, 0.f); v.w = fmaxf(v.w, 0.f);
            }
            *(float4*)&C[(size_t)r * N + c] = v;
        }
    }
}

// ---------------- aggregation (float4; R7 config: 128 threads, 2-edge unroll) ----------------
template<int D, int OSEL, int PRESCALE>
__global__ __launch_bounds__(128)
void agg4_kernel(float* __restrict__ outExt, const float* __restrict__ bias)
{
    constexpr int TPN = D / 4;
    constexpr int NPB = 128 / TPN;
    float* out;
    if constexpr (OSEL == 1) out = g_hcur;
    else out = outExt;

    const int lane = threadIdx.x % TPN;
    const int node = blockIdx.x * NPB + threadIdx.x / TPN;
    if (node >= N_NODES) return;

    const int s = g_row_ptr[node];
    const int e = g_row_ptr[node + 1];
    const float4* __restrict__ hp = (const float4*)g_hpre;

    float4 acc = make_float4(0.f, 0.f, 0.f, 0.f);
    int i = s;
    for (; i + 1 < e; i += 2) {
        int s0 = g_csr_src[i];
        int s1 = g_csr_src[i + 1];
        float4 v0 = hp[(size_t)s0 * TPN + lane];
        float4 v1 = hp[(size_t)s1 * TPN + lane];
        acc.x += v0.x; acc.y += v0.y; acc.z += v0.z; acc.w += v0.w;
        acc.x += v1.x; acc.y += v1.y; acc.z += v1.z; acc.w += v1.w;
    }
    if (i < e) {
        int s0 = g_csr_src[i];
        float4 v0 = hp[(size_t)s0 * TPN + lane];
        acc.x += v0.x; acc.y += v0.y; acc.z += v0.z; acc.w += v0.w;
    }

    const float sc = g_deg_in_inv[node];
    float osc = 1.0f;
    if constexpr (PRESCALE) osc = g_deg_out_inv[node];
    float4 bb = *(const float4*)&bias[lane * 4];
    float4 r;
    r.x = fmaxf(acc.x * sc + bb.x, 0.f) * osc;
    r.y = fmaxf(acc.y * sc + bb.y, 0.f) * osc;
    r.z = fmaxf(acc.z * sc + bb.z, 0.f) * osc;
    r.w = fmaxf(acc.w * sc + bb.w, 0.f) * osc;
    *(float4*)&out[(size_t)node * D + lane * 4] = r;
}

// ---------------- launch ----------------
extern "C" void kernel_launch(void* const* d_in, const int* in_sizes, int n_in,
                              void* d_out, int out_size)
{
    const float* x   = (const float*)d_in[0];
    const int*   ei  = (const int*)d_in[1];
    const float* W1  = (const float*)d_in[2];
    const float* b1  = (const float*)d_in[3];
    const float* W2  = (const float*)d_in[4];
    const float* b2  = (const float*)d_in[5];
    const float* W3  = (const float*)d_in[6];
    const float* b3  = (const float*)d_in[7];
    const float* mW1 = (const float*)d_in[8];
    const float* mb1 = (const float*)d_in[9];
    const float* mW2 = (const float*)d_in[10];
    const float* mb2 = (const float*)d_in[11];

    const int N = in_sizes[0] / D_IN;       // 50000
    const int E = in_sizes[1] / 2;          // 800000

    float* out      = (float*)d_out;
    float* h_last   = (float*)d_out + (size_t)N * D_OUT;

    const int T = 256;
    const int nbN = (N + T - 1) / T;
    const int nbE = (E + T - 1) / T;
    const int nbScan = (N + 1023) / 1024;
    const int tfRows = (N + 127) / 128;     // 391

    // ---- degrees + CSR build ----
    zero_counts_kernel<<<nbN, T>>>(N);
    degree_kernel<<<nbE, T>>>(ei, E);
    inv_kernel<<<nbN, T>>>(N);
    scan1_kernel<<<nbScan, 1024>>>(N);
    scan2_kernel<<<1, 32>>>(nbScan);
    scan3_kernel<<<nbScan, 1024>>>(N);
    copy_fill_kernel<<<nbN, T>>>(N);
    fill_csr_kernel<<<nbE, T>>>(ei, E);

    // ---- layer 1: hpre = (x * dout) @ W1 (rowscale fused in GEMM A-load) ----
    {
        dim3 grid(D_HID2 / 128, tfRows);
        gemm_tf32_kernel<128, 0, 1, 1><<<grid, 256>>>(x, W1, N, D_HID2, D_IN);
        agg4_kernel<D_HID2, 1, 1><<<(N + 1) / 2, 128>>>(nullptr, b1);
    }
    // ---- layer 2 ----
    {
        dim3 grid(D_HID2 / 128, tfRows);
        gemm_tf32_kernel<128, 1, 1, 0><<<grid, 256>>>(nullptr, W2, N, D_HID2, D_HID2);
        agg4_kernel<D_HID2, 1, 1><<<(N + 1) / 2, 128>>>(nullptr, b2);
    }
    // ---- layer 3: h_last (unscaled) directly into d_out ----
    {
        dim3 grid(D_HID / 128, tfRows);
        gemm_tf32_kernel<128, 1, 1, 0><<<grid, 256>>>(nullptr, W3, N, D_HID, D_HID2);
        agg4_kernel<D_HID, 0, 0><<<(N + 3) / 4, 128>>>(h_last, b3);
    }
    // ---- MLP layer 1 (tf32, raw GEMM into scratch) ----
    {
        dim3 grid(1, tfRows);
        gemm_tf32_kernel<64, 0, 2, 0><<<grid, 256>>>(h_last, mW1, N, D_MLP, D_HID);
    }
    // ---- MLP layer 2 (SIMT, A-side relu(a+mb1), guarded d_out store) ----
    {
        dim3 grid(D_OUT / 64, tfRows);
        gemm128_kernel<64, 2, 0, 1, 0, 1><<<grid, GTHREADS>>>(nullptr, mW2, out,
                                                              N, D_OUT, D_MLP, mb2, mb1);
    }
}

// round 10
// speedup vs baseline: 1.3557x; 1.0014x over previous
#include <cuda_runtime.h>
#include <cuda_bf16.h>
#include <mma.h>
#include <cstdint>

using namespace nvcuda;

#define N_NODES 50000
#define N_PAD   50048
#define N_EDGES 800000
#define D_IN    256
#define D_HID2  256
#define D_HID   128
#define D_MLP   64
#define D_OUT   64

// ---------------- scratch ----------------
__device__ float g_hpre[(size_t)N_PAD * D_HID2];
__device__ float g_hcur[(size_t)N_PAD * D_HID2];
__device__ float g_hidden[(size_t)N_PAD * D_MLP];
__device__ float g_deg_out_inv[N_NODES];
__device__ float g_deg_in_inv[N_NODES];
__device__ int   g_deg_out_cnt[N_NODES];
__device__ int   g_deg_in_cnt[N_NODES];
__device__ int   g_row_ptr[N_NODES + 1];
__device__ int   g_fill_ptr[N_NODES];
__device__ int   g_blk[64];
__device__ int   g_csr_src[N_EDGES];

template<int SEL>
__device__ __forceinline__ const float* select_in(const float* ext) {
    if constexpr (SEL == 1) return g_hcur;
    else if constexpr (SEL == 2) return g_hidden;
    else return ext;
}
template<int SEL>
__device__ __forceinline__ float* select_out(float* ext) {
    if constexpr (SEL == 1) return g_hpre;
    else if constexpr (SEL == 2) return g_hidden;
    else return ext;
}

// ---------------- degree / CSR ----------------

__global__ void zero_counts_kernel(int n) {
    int i = blockIdx.x * blockDim.x + threadIdx.x;
    if (i < n) { g_deg_out_cnt[i] = 0; g_deg_in_cnt[i] = 0; }
}

__global__ void degree_kernel(const int* __restrict__ ei, int E) {
    int e = blockIdx.x * blockDim.x + threadIdx.x;
    if (e < E) {
        atomicAdd(&g_deg_out_cnt[ei[e]], 1);
        atomicAdd(&g_deg_in_cnt[ei[E + e]], 1);
    }
}

__global__ void inv_kernel(int n) {
    int i = blockIdx.x * blockDim.x + threadIdx.x;
    if (i < n) {
        g_deg_out_inv[i] = rsqrtf(fmaxf((float)g_deg_out_cnt[i], 1.0f));
        g_deg_in_inv[i]  = rsqrtf(fmaxf((float)g_deg_in_cnt[i], 1.0f));
    }
}

__global__ void scan1_kernel(int n) {
    __shared__ int s[1024];
    int tid = threadIdx.x;
    int i = blockIdx.x * 1024 + tid;
    int v = (i < n) ? g_deg_in_cnt[i] : 0;
    s[tid] = v;
    __syncthreads();
    #pragma unroll
    for (int off = 1; off < 1024; off <<= 1) {
        int t = 0;
        if (tid >= off) t = s[tid - off];
        __syncthreads();
        s[tid] += t;
        __syncthreads();
    }
    if (i < n) g_row_ptr[i + 1] = s[tid];
    if (tid == 1023) g_blk[blockIdx.x] = s[1023];
}

__global__ void scan2_kernel(int nb) {
    if (threadIdx.x == 0 && blockIdx.x == 0) {
        int acc = 0;
        for (int i = 0; i < nb; i++) { int t = g_blk[i]; g_blk[i] = acc; acc += t; }
    }
}

__global__ void scan3_kernel(int n) {
    int i = blockIdx.x * 1024 + threadIdx.x;
    if (i < n) g_row_ptr[i + 1] += g_blk[blockIdx.x];
    if (i == 0) g_row_ptr[0] = 0;
}

__global__ void copy_fill_kernel(int n) {
    int i = blockIdx.x * blockDim.x + threadIdx.x;
    if (i < n) g_fill_ptr[i] = g_row_ptr[i];
}

__global__ void fill_csr_kernel(const int* __restrict__ ei, int E) {
    int e = blockIdx.x * blockDim.x + threadIdx.x;
    if (e < E) {
        int d = ei[E + e];
        int pos = atomicAdd(&g_fill_ptr[d], 1);
        g_csr_src[pos] = ei[e];
    }
}

// ---------------- tf32 WMMA GEMM: C = (A * rowscale?) @ B ----------------
// BM=128, BK=32, 256 threads, 8 warps (4x2). Warp tile 32 x (BN/2).
// tf32 RN rounding at smem store; register double-buffered.
template<int BN, int ASEL, int CSEL, int RS>
__global__ __launch_bounds__(256)
void gemm_tf32_kernel(const float* __restrict__ Aext, const float* __restrict__ B,
                      int M, int N, int K)
{
    constexpr int BM = 128, BK = 32;
    constexpr int LDA = BK + 8;      // 40
    constexpr int LDB = BN + 8;      // 136 / 72
    constexpr int WN  = BN / 2;
    constexpr int NF  = WN / 16;
    constexpr int BL  = BN / 32;
    constexpr int BC4 = BN / 4;

    const float* A = select_in<ASEL>(Aext);
    float* C = select_out<CSEL>(nullptr);

    __shared__ float As[BM][LDA];
    __shared__ float Bs[BK][LDB];

    const int tid  = threadIdx.x;
    const int warp = tid >> 5;
    const int wr   = warp >> 1;
    const int wc   = warp & 1;
    const int row0 = blockIdx.y * BM;
    const int col0 = blockIdx.x * BN;

    wmma::fragment<wmma::accumulator, 16, 16, 8, float> acc[2][NF];
    #pragma unroll
    for (int i = 0; i < 2; i++)
        #pragma unroll
        for (int j = 0; j < NF; j++) wmma::fill_fragment(acc[i][j], 0.0f);

    float4 aP[4], bP[BL];
    #pragma unroll
    for (int l = 0; l < 4; l++) {
        int lin = tid + l * 256;
        int r = lin >> 3, c4 = (lin & 7) << 2;
        int gr = row0 + r;
        float4 v = make_float4(0.f, 0.f, 0.f, 0.f);
        if (gr < M) {
            v = *(const float4*)&A[(size_t)gr * K + c4];
            if constexpr (RS) {
                float sc = g_deg_out_inv[gr];
                v.x *= sc; v.y *= sc; v.z *= sc; v.w *= sc;
            }
        }
        aP[l] = v;
    }
    #pragma unroll
    for (int l = 0; l < BL; l++) {
        int lin = tid + l * 256;
        int r = lin / BC4, c4 = (lin % BC4) * 4;
        bP[l] = *(const float4*)&B[(size_t)r * N + col0 + c4];
    }

    for (int k0 = 0; k0 < K; k0 += BK) {
        #pragma unroll
        for (int l = 0; l < 4; l++) {
            int lin = tid + l * 256;
            int r = lin >> 3, c4 = (lin & 7) << 2;
            As[r][c4 + 0] = wmma::__float_to_tf32(aP[l].x);
            As[r][c4 + 1] = wmma::__float_to_tf32(aP[l].y);
            As[r][c4 + 2] = wmma::__float_to_tf32(aP[l].z);
            As[r][c4 + 3] = wmma::__float_to_tf32(aP[l].w);
        }
        #pragma unroll
        for (int l = 0; l < BL; l++) {
            int lin = tid + l * 256;
            int r = lin / BC4, c4 = (lin % BC4) * 4;
            Bs[r][c4 + 0] = wmma::__float_to_tf32(bP[l].x);
            Bs[r][c4 + 1] = wmma::__float_to_tf32(bP[l].y);
            Bs[r][c4 + 2] = wmma::__float_to_tf32(bP[l].z);
            Bs[r][c4 + 3] = wmma::__float_to_tf32(bP[l].w);
        }
        __syncthreads();

        if (k0 + BK < K) {
            #pragma unroll
            for (int l = 0; l < 4; l++) {
                int lin = tid + l * 256;
                int r = lin >> 3, c4 = (lin & 7) << 2;
                int gr = row0 + r;
                float4 v = make_float4(0.f, 0.f, 0.f, 0.f);
                if (gr < M) {
                    v = *(const float4*)&A[(size_t)gr * K + (k0 + BK) + c4];
                    if constexpr (RS) {
                        float sc = g_deg_out_inv[gr];
                        v.x *= sc; v.y *= sc; v.z *= sc; v.w *= sc;
                    }
                }
                aP[l] = v;
            }
            #pragma unroll
            for (int l = 0; l < BL; l++) {
                int lin = tid + l * 256;
                int r = lin / BC4, c4 = (lin % BC4) * 4;
                bP[l] = *(const float4*)&B[(size_t)(k0 + BK + r) * N + col0 + c4];
            }
        }

        #pragma unroll
        for (int kk = 0; kk < BK; kk += 8) {
            wmma::fragment<wmma::matrix_a, 16, 16, 8, wmma::precision::tf32, wmma::row_major> af[2];
            #pragma unroll
            for (int i = 0; i < 2; i++)
                wmma::load_matrix_sync(af[i], &As[wr * 32 + i * 16][kk], LDA);
            wmma::fragment<wmma::matrix_b, 16, 16, 8, wmma::precision::tf32, wmma::row_major> bf[NF];
            #pragma unroll
            for (int j = 0; j < NF; j++)
                wmma::load_matrix_sync(bf[j], &Bs[kk][wc * WN + j * 16], LDB);
            #pragma unroll
            for (int i = 0; i < 2; i++)
                #pragma unroll
                for (int j = 0; j < NF; j++)
                    wmma::mma_sync(acc[i][j], af[i], bf[j], acc[i][j]);
        }
        __syncthreads();
    }

    #pragma unroll
    for (int i = 0; i < 2; i++)
        #pragma unroll
        for (int j = 0; j < NF; j++) {
            int r = row0 + wr * 32 + i * 16;
            int c = col0 + wc * WN + j * 16;
            wmma::store_matrix_sync(&C[(size_t)r * N + c], acc[i][j], N, wmma::mem_row_major);
        }
}

// ---------------- SIMT GEMM (final MLP layer; guarded d_out store) ----------------
#define GTHREADS 256
template<int BN, int ASEL, int CSEL, int USE_BIAS, int DO_RELU, int ABR>
__global__ __launch_bounds__(GTHREADS)
void gemm128_kernel(const float* __restrict__ Aext, const float* __restrict__ B,
                    float* __restrict__ Cext, int M, int N, int K,
                    const float* __restrict__ bias, const float* __restrict__ abias)
{
    constexpr int BM = 128;
    constexpr int BK = 8;
    constexpr int TM = 8;
    constexpr int TN = BN / 16;

    const float* A = select_in<ASEL>(Aext);
    float* C = select_out<CSEL>(Cext);

    __shared__ float As[BK][BM + 4];
    __shared__ float Bs[BK][BN];

    const int tid = threadIdx.x;
    const int tx = tid % 16;
    const int ty = tid / 16;
    const int row0 = blockIdx.y * BM;
    const int col0 = blockIdx.x * BN;

    const int arow = tid / 2;
    const int ac4  = (tid % 2) * 4;
    const int gA   = row0 + arow;

    const int brow = (BN == 128) ? (tid / 32) : (tid / 16);
    const int bc4  = (BN == 128) ? ((tid % 32) * 4) : ((tid % 16) * 4);
    const bool bactive = (BN == 128) ? true : (tid < 128);

    float acc[TM][TN];
    #pragma unroll
    for (int i = 0; i < TM; i++)
        #pragma unroll
        for (int j = 0; j < TN; j++) acc[i][j] = 0.0f;

    float4 av = make_float4(0.f, 0.f, 0.f, 0.f);
    if (gA < M) {
        av = *(const float4*)&A[(size_t)gA * K + ac4];
        if constexpr (ABR) {
            av.x = fmaxf(av.x + abias[ac4 + 0], 0.f);
            av.y = fmaxf(av.y + abias[ac4 + 1], 0.f);
            av.z = fmaxf(av.z + abias[ac4 + 2], 0.f);
            av.w = fmaxf(av.w + abias[ac4 + 3], 0.f);
        }
    }
    float4 bv = make_float4(0.f, 0.f, 0.f, 0.f);
    if (bactive) bv = *(const float4*)&B[(size_t)brow * N + col0 + bc4];

    for (int k0 = 0; k0 < K; k0 += BK) {
        As[ac4 + 0][arow] = av.x;
        As[ac4 + 1][arow] = av.y;
        As[ac4 + 2][arow] = av.z;
        As[ac4 + 3][arow] = av.w;
        if (bactive) *(float4*)&Bs[brow][bc4] = bv;
        __syncthreads();

        if (k0 + BK < K) {
            av = make_float4(0.f, 0.f, 0.f, 0.f);
            if (gA < M) {
                av = *(const float4*)&A[(size_t)gA * K + (k0 + BK) + ac4];
                if constexpr (ABR) {
                    av.x = fmaxf(av.x + abias[k0 + BK + ac4 + 0], 0.f);
                    av.y = fmaxf(av.y + abias[k0 + BK + ac4 + 1], 0.f);
                    av.z = fmaxf(av.z + abias[k0 + BK + ac4 + 2], 0.f);
                    av.w = fmaxf(av.w + abias[k0 + BK + ac4 + 3], 0.f);
                }
            }
            if (bactive) bv = *(const float4*)&B[(size_t)(k0 + BK + brow) * N + col0 + bc4];
        }

        #pragma unroll
        for (int k = 0; k < BK; k++) {
            float a[TM], b[TN];
            #pragma unroll
            for (int q = 0; q < TM / 4; q++)
                *(float4*)&a[q * 4] = *(const float4*)&As[k][ty * TM + q * 4];
            #pragma unroll
            for (int q = 0; q < TN / 4; q++)
                *(float4*)&b[q * 4] = *(const float4*)&Bs[k][tx * TN + q * 4];
            #pragma unroll
            for (int i = 0; i < TM; i++)
                #pragma unroll
                for (int j = 0; j < TN; j++)
                    acc[i][j] += a[i] * b[j];
        }
        __syncthreads();
    }

    #pragma unroll
    for (int i = 0; i < TM; i++) {
        int r = row0 + ty * TM + i;
        if (r >= M) continue;
        #pragma unroll
        for (int j = 0; j < TN; j += 4) {
            int c = col0 + tx * TN + j;
            float4 v = *(float4*)&acc[i][j];
            if constexpr (USE_BIAS) {
                v.x += bias[c + 0]; v.y += bias[c + 1];
                v.z += bias[c + 2]; v.w += bias[c + 3];
            }
            if constexpr (DO_RELU) {
                v.x = fmaxf(v.x, 0.f); v.y = fmaxf(v.y, 0.f);
                v.z = fmaxf(v.z, 0.f); v.w = fmaxf(v.w, 0.f);
            }
            *(float4*)&C[(size_t)r * N + c] = v;
        }
    }
}

// ---------------- aggregation (float4; 128 threads; 4-edge unroll, 2 accumulators) ----------------
template<int D, int OSEL, int PRESCALE>
__global__ __launch_bounds__(128)
void agg4_kernel(float* __restrict__ outExt, const float* __restrict__ bias)
{
    constexpr int TPN = D / 4;
    constexpr int NPB = 128 / TPN;
    float* out;
    if constexpr (OSEL == 1) out = g_hcur;
    else out = outExt;

    const int lane = threadIdx.x % TPN;
    const int node = blockIdx.x * NPB + threadIdx.x / TPN;
    if (node >= N_NODES) return;

    const int s = g_row_ptr[node];
    const int e = g_row_ptr[node + 1];
    const float4* __restrict__ hp = (const float4*)g_hpre;
    const int* __restrict__ csr = g_csr_src;

    float4 acc0 = make_float4(0.f, 0.f, 0.f, 0.f);
    float4 acc1 = make_float4(0.f, 0.f, 0.f, 0.f);
    int i = s;
    for (; i + 3 < e; i += 4) {
        int s0 = csr[i];
        int s1 = csr[i + 1];
        int s2 = csr[i + 2];
        int s3 = csr[i + 3];
        float4 v0 = hp[(size_t)s0 * TPN + lane];
        float4 v1 = hp[(size_t)s1 * TPN + lane];
        float4 v2 = hp[(size_t)s2 * TPN + lane];
        float4 v3 = hp[(size_t)s3 * TPN + lane];
        acc0.x += v0.x; acc0.y += v0.y; acc0.z += v0.z; acc0.w += v0.w;
        acc1.x += v1.x; acc1.y += v1.y; acc1.z += v1.z; acc1.w += v1.w;
        acc0.x += v2.x; acc0.y += v2.y; acc0.z += v2.z; acc0.w += v2.w;
        acc1.x += v3.x; acc1.y += v3.y; acc1.z += v3.z; acc1.w += v3.w;
    }
    for (; i < e; i++) {
        int s0 = csr[i];
        float4 v0 = hp[(size_t)s0 * TPN + lane];
        acc0.x += v0.x; acc0.y += v0.y; acc0.z += v0.z; acc0.w += v0.w;
    }
    acc0.x += acc1.x; acc0.y += acc1.y; acc0.z += acc1.z; acc0.w += acc1.w;

    const float sc = g_deg_in_inv[node];
    float osc = 1.0f;
    if constexpr (PRESCALE) osc = g_deg_out_inv[node];
    float4 bb = *(const float4*)&bias[lane * 4];
    float4 r;
    r.x = fmaxf(acc0.x * sc + bb.x, 0.f) * osc;
    r.y = fmaxf(acc0.y * sc + bb.y, 0.f) * osc;
    r.z = fmaxf(acc0.z * sc + bb.z, 0.f) * osc;
    r.w = fmaxf(acc0.w * sc + bb.w, 0.f) * osc;
    *(float4*)&out[(size_t)node * D + lane * 4] = r;
}

// ---------------- launch ----------------
extern "C" void kernel_launch(void* const* d_in, const int* in_sizes, int n_in,
                              void* d_out, int out_size)
{
    const float* x   = (const float*)d_in[0];
    const int*   ei  = (const int*)d_in[1];
    const float* W1  = (const float*)d_in[2];
    const float* b1  = (const float*)d_in[3];
    const float* W2  = (const float*)d_in[4];
    const float* b2  = (const float*)d_in[5];
    const float* W3  = (const float*)d_in[6];
    const float* b3  = (const float*)d_in[7];
    const float* mW1 = (const float*)d_in[8];
    const float* mb1 = (const float*)d_in[9];
    const float* mW2 = (const float*)d_in[10];
    const float* mb2 = (const float*)d_in[11];

    const int N = in_sizes[0] / D_IN;       // 50000
    const int E = in_sizes[1] / 2;          // 800000

    float* out      = (float*)d_out;
    float* h_last   = (float*)d_out + (size_t)N * D_OUT;

    const int T = 256;
    const int nbN = (N + T - 1) / T;
    const int nbE = (E + T - 1) / T;
    const int nbScan = (N + 1023) / 1024;
    const int tfRows = (N + 127) / 128;     // 391

    // ---- degrees (needed by layer-1 GEMM) ----
    zero_counts_kernel<<<nbN, T>>>(N);
    degree_kernel<<<nbE, T>>>(ei, E);
    inv_kernel<<<nbN, T>>>(N);

    // ---- layer-1 GEMM hoisted to 4th launch (gets ncu-profiled; only needs deg_out_inv) ----
    {
        dim3 grid(D_HID2 / 128, tfRows);
        gemm_tf32_kernel<128, 0, 1, 1><<<grid, 256>>>(x, W1, N, D_HID2, D_IN);
    }

    // ---- CSR build (independent of GEMM; must finish before agg1) ----
    scan1_kernel<<<nbScan, 1024>>>(N);
    scan2_kernel<<<1, 32>>>(nbScan);
    scan3_kernel<<<nbScan, 1024>>>(N);
    copy_fill_kernel<<<nbN, T>>>(N);
    fill_csr_kernel<<<nbE, T>>>(ei, E);

    // ---- layer 1 aggregation ----
    agg4_kernel<D_HID2, 1, 1><<<(N + 1) / 2, 128>>>(nullptr, b1);

    // ---- layer 2 ----
    {
        dim3 grid(D_HID2 / 128, tfRows);
        gemm_tf32_kernel<128, 1, 1, 0><<<grid, 256>>>(nullptr, W2, N, D_HID2, D_HID2);
        agg4_kernel<D_HID2, 1, 1><<<(N + 1) / 2, 128>>>(nullptr, b2);
    }
    // ---- layer 3: h_last (unscaled) directly into d_out ----
    {
        dim3 grid(D_HID / 128, tfRows);
        gemm_tf32_kernel<128, 1, 1, 0><<<grid, 256>>>(nullptr, W3, N, D_HID, D_HID2);
        agg4_kernel<D_HID, 0, 0><<<(N + 3) / 4, 128>>>(h_last, b3);
    }
    // ---- MLP layer 1 (tf32, raw GEMM into scratch) ----
    {
        dim3 grid(1, tfRows);
        gemm_tf32_kernel<64, 0, 2, 0><<<grid, 256>>>(h_last, mW1, N, D_MLP, D_HID);
    }
    // ---- MLP layer 2 (SIMT, A-side relu(a+mb1), guarded d_out store) ----
    {
        dim3 grid(D_OUT / 64, tfRows);
        gemm128_kernel<64, 2, 0, 1, 0, 1><<<grid, GTHREADS>>>(nullptr, mW2, out,
                                                              N, D_OUT, D_MLP, mb2, mb1);
    }
}